// round 3
// baseline (speedup 1.0000x reference)
#include <cuda_runtime.h>

// ---------------------------------------------------------------------------
// Problem constants
// ---------------------------------------------------------------------------
#define Bc    8
#define Ac    60000
#define Cc    150                 // 1 + (10+19+39+69+12)
#define Gc    20
#define Tc    5
#define BAc   (Bc * Ac)           // 480,000 anchors
#define NCONF (BAc * Cc)          // 72,000,000
#define NV4   (NCONF / 4)         // 18,000,000 float4s
#define NV4H  (NV4 / 2)           // 9,000,000 (half-range split)
#define RW    8                   // padded words per bitmask row
#define NROWS (Bc * (Gc + 1))     // 168 rows
#define GRIDM 1184                // 148 SMs * 8 blocks

#define L2E   1.44269504088896341f   // log2(e)
#define C0w   (-0.75f * 0.69314718056f)  // -alpha' * ln2, label 0
#define C1w   (-0.25f * 0.69314718056f)  // -alpha' * ln2, label 1

__device__ unsigned g_bits[NROWS * RW];
__device__ double   g_acc[3];     // [0]=reg_sum, [1]=cls_sum, [2]=num_pos

// ---------------------------------------------------------------------------
// Kernel 1: build per-(b, lb) 150-bit label masks.
// Stage gt_labels (4000 ints) into smem first so mask building hits smem,
// not a 25-deep DRAM latency chain per thread.
// ---------------------------------------------------------------------------
__global__ void init_kernel(const int* __restrict__ gt_labels) {
    __shared__ int gl[Bc * Gc * 5 * Tc];      // 4000 ints = 16 KB
    int tid = threadIdx.x;
    for (int i = tid; i < Bc * Gc * 5 * Tc; i += 256)
        gl[i] = gt_labels[i];
    if (tid < 3) g_acc[tid] = 0.0;
    __syncthreads();

    if (tid < NROWS) {
        int b = tid / (Gc + 1), g = tid % (Gc + 1);
        unsigned w[RW] = {0u, 0u, 0u, 0u, 0u, 0u, 0u, 0u};
        if (g > 0) {
            w[0] = 1u;                                // bit 0: lb>0 positive
            const int off[5] = {1, 11, 30, 69, 138};  // 1 + head offsets
            int grp = g - 1;
#pragma unroll
            for (int h = 0; h < 5; h++) {
#pragma unroll
                for (int t = 0; t < Tc; t++) {
                    int v = gl[((b * Gc + grp) * 5 + h) * Tc + t];
                    if (v >= 0) {
                        int bit = off[h] + v;
                        w[bit >> 5] |= (1u << (bit & 31));
                    }
                }
            }
        }
#pragma unroll
        for (int k = 0; k < RW; k++)
            g_bits[tid * RW + k] = w[k];
    }
}

// ---------------------------------------------------------------------------
// Focal term, unified over labels via input sign flip:
//   term(x, l) = A(l) * softplus(s) * sigma(s)^2,  s = l ? -x : x
// With s2 = s*log2(e):  u = 2^s2,  r = 1/(1+u),  lr = log2(r)  (<= 0)
//   softplus(s) = -ln2 * lr,  sigma(s) = u * r
//   term = coef * lr * (u*r)^2,  coef = -A*ln2*mask  (folded, passed in)
// ---------------------------------------------------------------------------
__device__ __forceinline__ float mufu_ex2(float x) {
    float y; asm("ex2.approx.f32 %0, %1;" : "=f"(y) : "f"(x)); return y;
}
__device__ __forceinline__ float mufu_lg2(float x) {
    float y; asm("lg2.approx.f32 %0, %1;" : "=f"(y) : "f"(x)); return y;
}
__device__ __forceinline__ float mufu_rcp(float x) {
    float y; asm("rcp.approx.f32 %0, %1;" : "=f"(y) : "f"(x)); return y;
}

__device__ __forceinline__ void focal(float x2, unsigned sbit, float coef,
                                      float& acc) {
    float s  = __uint_as_float(__float_as_uint(x2) ^ sbit);  // ALU (LOP3)
    float u  = mufu_ex2(s);
    float r  = mufu_rcp(1.0f + u);
    float lr = mufu_lg2(r);
    float q  = u * r;
    acc = fmaf(coef * lr, q * q, acc);
}

// ---------------------------------------------------------------------------
// Main classification pass over float4 range [lo, hi).
// ---------------------------------------------------------------------------
__device__ __forceinline__ void cls_body(const float4* __restrict__ conf4,
                                         const int* __restrict__ lbin,
                                         const unsigned* __restrict__ sb,
                                         int lo, int hi, int tid, int stride,
                                         float& cls0, float& cls1,
                                         float& cls2, float& cls3) {
#pragma unroll 4
    for (int i = lo + tid; i < hi; i += stride) {
        float4 v = __ldcs(&conf4[i]);
        unsigned base = (unsigned)i << 2;
        unsigned a = base / (unsigned)Cc;     // magic-mul
        int c = (int)(base - a * Cc);         // even, 0..148
        unsigned b = a / (unsigned)Ac;
        int lb = __ldg(&lbin[a]);
        int row = (int)b * (Gc + 1) + max(lb, 0);

        const unsigned* rp = &sb[row * RW + (c >> 5)];
        unsigned bits = __funnelshift_r(rp[0], rp[1], c);
        float m01 = (lb >= 0) ? 1.f : 0.f;
        float m23 = m01;

        if (c == 148) {                       // rare anchor crossing (2+2)
            unsigned a2 = a + 1;
            int lb2 = __ldg(&lbin[a2]);
            unsigned b2 = a2 / (unsigned)Ac;
            int row2 = (int)b2 * (Gc + 1) + max(lb2, 0);
            bits = (bits & 3u) | ((sb[row2 * RW] & 3u) << 2);
            m23 = (lb2 >= 0) ? 1.f : 0.f;
        }

        // per-lane sign bits (ALU) and coefficients
        unsigned s0 = (bits << 31);
        unsigned s1 = (bits << 30) & 0x80000000u;
        unsigned s2 = (bits << 29) & 0x80000000u;
        unsigned s3 = (bits << 28) & 0x80000000u;
        float c0 = (s0 ? C1w : C0w) * m01;
        float c1 = (s1 ? C1w : C0w) * m01;
        float c2 = (s2 ? C1w : C0w) * m23;
        float c3 = (s3 ? C1w : C0w) * m23;

        focal(v.x * L2E, s0, c0, cls0);
        focal(v.y * L2E, s1, c1, cls1);
        focal(v.z * L2E, s2, c2, cls2);
        focal(v.w * L2E, s3, c3, cls3);
    }
}

__device__ __forceinline__ void block_reduce_commit(float reg, float cls,
                                                    float npos) {
#pragma unroll
    for (int o = 16; o > 0; o >>= 1) {
        cls  += __shfl_down_sync(0xFFFFFFFFu, cls,  o);
        reg  += __shfl_down_sync(0xFFFFFFFFu, reg,  o);
        npos += __shfl_down_sync(0xFFFFFFFFu, npos, o);
    }
    __shared__ float red[3][8];
    int warp = threadIdx.x >> 5, lane = threadIdx.x & 31;
    if (lane == 0) { red[0][warp] = reg; red[1][warp] = cls; red[2][warp] = npos; }
    __syncthreads();
    if (threadIdx.x == 0) {
        float r0 = 0.f, r1 = 0.f, r2 = 0.f;
#pragma unroll
        for (int w = 0; w < 8; w++) { r0 += red[0][w]; r1 += red[1][w]; r2 += red[2][w]; }
        if (r0 != 0.f) atomicAdd(&g_acc[0], (double)r0);
        atomicAdd(&g_acc[1], (double)r1);
        if (r2 != 0.f) atomicAdd(&g_acc[2], (double)r2);
    }
}

// ---------------------------------------------------------------------------
// Kernel 2a: first half of classification.
// ---------------------------------------------------------------------------
__global__ void __launch_bounds__(256)
mainA_kernel(const float4* __restrict__ conf4, const int* __restrict__ lbin) {
    __shared__ unsigned sb[NROWS * RW];
    for (int i = threadIdx.x; i < NROWS * RW; i += 256) sb[i] = g_bits[i];
    __syncthreads();

    const int tid = blockIdx.x * 256 + threadIdx.x;
    float c0 = 0.f, c1 = 0.f, c2 = 0.f, c3 = 0.f;
    cls_body(conf4, lbin, sb, 0, NV4H, tid, GRIDM * 256, c0, c1, c2, c3);
    block_reduce_commit(0.f, (c0 + c1) + (c2 + c3), 0.f);
}

// ---------------------------------------------------------------------------
// Kernel 2b: second half of classification + regression + pos count.
// ---------------------------------------------------------------------------
__global__ void __launch_bounds__(256)
mainB_kernel(const float4* __restrict__ conf4,
             const float4* __restrict__ pred4,
             const float4* __restrict__ gt4,
             const int*    __restrict__ lbin) {
    __shared__ unsigned sb[NROWS * RW];
    for (int i = threadIdx.x; i < NROWS * RW; i += 256) sb[i] = g_bits[i];
    __syncthreads();

    const int tid    = blockIdx.x * 256 + threadIdx.x;
    const int stride = GRIDM * 256;
    float c0 = 0.f, c1 = 0.f, c2 = 0.f, c3 = 0.f;
    cls_body(conf4, lbin, sb, NV4H, NV4, tid, stride, c0, c1, c2, c3);

    float reg = 0.f, npos = 0.f;
    for (int a = tid; a < BAc; a += stride) {
        int lb = __ldg(&lbin[a]);
        if (lb > 0) {
            npos += 1.0f;
            float4 p = pred4[a];
            float4 g = gt4[a];
            float d[4] = {p.x - g.x, p.y - g.y, p.z - g.z, p.w - g.w};
#pragma unroll
            for (int k = 0; k < 4; k++) {
                float n = fabsf(d[k]);
                reg += (n < (1.0f / 9.0f)) ? 4.5f * n * n : n - (1.0f / 18.0f);
            }
        }
    }
    block_reduce_commit(reg, (c0 + c1) + (c2 + c3), npos);
}

// ---------------------------------------------------------------------------
// Kernel 3: finalize.
// ---------------------------------------------------------------------------
__global__ void finalize_kernel(float* __restrict__ out) {
    double np = g_acc[2];
    if (np < 1.0) np = 1.0;
    out[0] = (float)(g_acc[0] / (np * 4.0));
    out[1] = (float)(g_acc[1] / (np * 6.0));
}

extern "C" void kernel_launch(void* const* d_in, const int* in_sizes, int n_in,
                              void* d_out, int out_size) {
    const float* conf       = (const float*)d_in[0];   // (8, 60000, 150) f32
    const float* pred       = (const float*)d_in[1];   // (8, 60000, 4)   f32
    const float* gt_loc     = (const float*)d_in[2];   // (8, 60000, 4)   f32
    const int*   gt_labels  = (const int*)  d_in[3];   // (8, 20, 5, 5)   i32
    // d_in[4] = counts: not used by the computation
    const int*   labels_bin = (const int*)  d_in[5];   // (8, 60000)      i32
    float* out = (float*)d_out;

    init_kernel<<<1, 256>>>(gt_labels);

    mainA_kernel<<<GRIDM, 256>>>((const float4*)conf, labels_bin);
    mainB_kernel<<<GRIDM, 256>>>((const float4*)conf,
                                 (const float4*)pred,
                                 (const float4*)gt_loc,
                                 labels_bin);

    finalize_kernel<<<1, 1>>>(out);
}